// round 1
// baseline (speedup 1.0000x reference)
#include <cuda_runtime.h>

#define TWO_N   8192
#define NHALF   4096
#define DD      256
#define BM      32
#define BN      256
#define BK      16
#define NTHR    256
#define BSTRIDE 260   // padded B tile row stride (floats)

// 8 MB scratch for normalized rows, 256 per-block partials
__device__ float g_zn[TWO_N * DD];
__device__ float g_part[TWO_N / BM];

// packed fp32x2 FMA (sm_100+): d = a*b + d on two lanes
#define FMA2(d, a, b) \
    asm("fma.rn.f32x2 %0, %1, %2, %0;" : "+l"(d) : "l"(a), "l"(b))

// ---------------------------------------------------------------------------
// Kernel 1: L2-normalize rows of concat(z1, z2) -> g_zn
// one block (64 threads) per row, float4 I/O
// ---------------------------------------------------------------------------
__global__ void norm_kernel(const float* __restrict__ z1,
                            const float* __restrict__ z2) {
    int row = blockIdx.x;
    const float* src = (row < NHALF) ? (z1 + (size_t)row * DD)
                                     : (z2 + (size_t)(row - NHALF) * DD);
    int t = threadIdx.x;  // 0..63
    float4 v = reinterpret_cast<const float4*>(src)[t];
    float ss = v.x * v.x + v.y * v.y + v.z * v.z + v.w * v.w;
#pragma unroll
    for (int o = 16; o; o >>= 1) ss += __shfl_xor_sync(0xffffffffu, ss, o);
    __shared__ float ws[2];
    if ((t & 31) == 0) ws[t >> 5] = ss;
    __syncthreads();
    float tot = ws[0] + ws[1];
    float inv = 1.0f / fmaxf(sqrtf(tot), 1e-8f);
    float4 o4 = make_float4(v.x * inv, v.y * inv, v.z * inv, v.w * inv);
    reinterpret_cast<float4*>(g_zn + (size_t)row * DD)[t] = o4;
}

// ---------------------------------------------------------------------------
// Kernel 2: per-row  log(sum_{j!=i} exp(2*zn_i.zn_j))  and positive term,
// fused into one GEMM sweep. Block = 32 rows x all 8192 cols.
// ---------------------------------------------------------------------------
__device__ __forceinline__ void loadB_ldg(float4* rv, const float* __restrict__ zn,
                                          int cb, int kc, int tid) {
#pragma unroll
    for (int i = 0; i < 4; i++) {
        int lin = i * NTHR + tid;      // 0..1023
        int col = lin >> 2;            // 0..255
        int k4  = lin & 3;             // 0..3
        rv[i] = *reinterpret_cast<const float4*>(
            zn + (size_t)(cb + col) * DD + kc + (k4 << 2));
    }
}

__device__ __forceinline__ void storeB_sts(float* Bbuf, const float4* rv, int tid) {
#pragma unroll
    for (int i = 0; i < 4; i++) {
        int lin = i * NTHR + tid;
        int col = lin >> 2;
        int k4  = lin & 3;
        int b0  = (k4 << 2) * BSTRIDE + col;   // Bs[k_local][col], transposed
        Bbuf[b0]               = rv[i].x;
        Bbuf[b0 + BSTRIDE]     = rv[i].y;
        Bbuf[b0 + 2 * BSTRIDE] = rv[i].z;
        Bbuf[b0 + 3 * BSTRIDE] = rv[i].w;
    }
}

__global__ void __launch_bounds__(NTHR, 2) sim_kernel() {
    extern __shared__ float smem[];
    float* As = smem;                     // [BM][DD] = 32 x 256, row-major
    float* Bs = smem + BM * DD;           // [2][BK][BSTRIDE] double buffer

    const float* zn = g_zn;
    int tid = threadIdx.x;
    int ty  = tid >> 5;                   // warp 0..7  -> row group
    int tx  = tid & 31;                   // lane       -> col group
    int rbase = blockIdx.x * BM;
    int r0 = ty * 4;                      // first local row of this thread

    // load A tile (32 rows x 256) into SMEM, float4, coalesced
#pragma unroll
    for (int i = 0; i < 8; i++) {
        int lin = i * NTHR + tid;         // 0..2047 float4s
        int row = lin >> 6;
        int k4  = lin & 63;
        float4 v = *reinterpret_cast<const float4*>(
            zn + (size_t)(rbase + row) * DD + (k4 << 2));
        *reinterpret_cast<float4*>(As + row * DD + (k4 << 2)) = v;
    }
    __syncthreads();

    float rowsum[4] = {0.f, 0.f, 0.f, 0.f};
    float possum[4] = {0.f, 0.f, 0.f, 0.f};
    float4 rv[4];

#pragma unroll 1
    for (int cb = 0; cb < TWO_N; cb += BN) {
        unsigned long long acc[4][4];
#pragma unroll
        for (int r = 0; r < 4; r++)
#pragma unroll
            for (int p = 0; p < 4; p++) acc[r][p] = 0ull;   // two +0.0f

        // prefetch k-chunk 0
        loadB_ldg(rv, zn, cb, 0, tid);
        storeB_sts(Bs, rv, tid);
        __syncthreads();

#pragma unroll 1
        for (int c = 0; c < DD / BK; c++) {               // 16 chunks of k
            if (c + 1 < DD / BK) loadB_ldg(rv, zn, cb, (c + 1) * BK, tid);
            const float* Bc = Bs + (c & 1) * (BK * BSTRIDE);
#pragma unroll
            for (int kb = 0; kb < BK; kb++) {
                int k = c * BK + kb;
                unsigned long long a2[4];
#pragma unroll
                for (int r = 0; r < 4; r++) {
                    unsigned int au = __float_as_uint(As[(r0 + r) * DD + k]);
                    asm("mov.b64 %0, {%1, %1};" : "=l"(a2[r]) : "r"(au));
                }
                ulonglong2 b01 = *reinterpret_cast<const ulonglong2*>(
                    Bc + kb * BSTRIDE + (tx << 2));
                ulonglong2 b23 = *reinterpret_cast<const ulonglong2*>(
                    Bc + kb * BSTRIDE + 128 + (tx << 2));
#pragma unroll
                for (int r = 0; r < 4; r++) {
                    FMA2(acc[r][0], a2[r], b01.x);
                    FMA2(acc[r][1], a2[r], b01.y);
                    FMA2(acc[r][2], a2[r], b23.x);
                    FMA2(acc[r][3], a2[r], b23.y);
                }
            }
            __syncthreads();                               // done reading buf
            if (c + 1 < DD / BK) {
                storeB_sts(Bs + ((c + 1) & 1) * (BK * BSTRIDE), rv, tid);
                __syncthreads();                           // writes visible
            }
        }

        // epilogue: stream exp() into per-row accumulators
#pragma unroll
        for (int r = 0; r < 4; r++) {
            int row  = rbase + r0 + r;
            int pcol = row ^ NHALF;                        // positive pair col
#pragma unroll
            for (int p = 0; p < 4; p++) {
                unsigned int ulo, uhi;
                asm("mov.b64 {%0, %1}, %2;" : "=r"(ulo), "=r"(uhi) : "l"(acc[r][p]));
                float slo = 2.0f * __uint_as_float(ulo);   // sim = dot / T
                float shi = 2.0f * __uint_as_float(uhi);
                int colbase = cb + ((p < 2) ? 0 : 128) + (tx << 2) + ((p & 1) << 1);
                if (colbase != row)         rowsum[r] += __expf(slo);
                if (colbase == pcol)        possum[r] += slo;
                if (colbase + 1 != row)     rowsum[r] += __expf(shi);
                if (colbase + 1 == pcol)    possum[r] += shi;
            }
        }
    }

    // reduce across lanes (columns), then across warps -> per-block partial
    float local = 0.f;
#pragma unroll
    for (int r = 0; r < 4; r++) {
        float rs = rowsum[r], ps = possum[r];
#pragma unroll
        for (int o = 16; o; o >>= 1) {
            rs += __shfl_xor_sync(0xffffffffu, rs, o);
            ps += __shfl_xor_sync(0xffffffffu, ps, o);
        }
        if (tx == 0) local += logf(rs) - ps;
    }
    __shared__ float wsum[8];
    if (tx == 0) wsum[ty] = local;
    __syncthreads();
    if (tid == 0) {
        float s = 0.f;
#pragma unroll
        for (int w = 0; w < 8; w++) s += wsum[w];
        g_part[blockIdx.x] = s;
    }
}

// ---------------------------------------------------------------------------
// Kernel 3: reduce 256 partials -> loss scalar
// ---------------------------------------------------------------------------
__global__ void finish_kernel(float* __restrict__ out) {
    int t = threadIdx.x;                  // 256 threads
    float v = g_part[t];
#pragma unroll
    for (int o = 16; o; o >>= 1) v += __shfl_xor_sync(0xffffffffu, v, o);
    __shared__ float red[8];
    if ((t & 31) == 0) red[t >> 5] = v;
    __syncthreads();
    if (t == 0) {
        float s = 0.f;
#pragma unroll
        for (int w = 0; w < 8; w++) s += red[w];
        out[0] = s / (float)TWO_N;
    }
}

// ---------------------------------------------------------------------------
extern "C" void kernel_launch(void* const* d_in, const int* in_sizes, int n_in,
                              void* d_out, int out_size) {
    const float* z1 = (const float*)d_in[0];
    const float* z2 = (const float*)d_in[1];
    float* out = (float*)d_out;

    norm_kernel<<<TWO_N, 64>>>(z1, z2);

    size_t smem = (size_t)(BM * DD + 2 * BK * BSTRIDE) * sizeof(float);  // ~64.5 KB
    cudaFuncSetAttribute(sim_kernel, cudaFuncAttributeMaxDynamicSharedMemorySize,
                         (int)smem);
    sim_kernel<<<TWO_N / BM, NTHR, smem>>>();

    finish_kernel<<<1, 256>>>(out);
}

// round 4
// speedup vs baseline: 8.9535x; 8.9535x over previous
#include <cuda_runtime.h>
#include <cuda_bf16.h>
#include <cstdint>

#define TWO_N 8192
#define NHALF 4096
#define DDIM  256
#define BM 128
#define BN 128
#define NTILES 32            // 4096 cols per CTA-half / 128
#define NTHR 256             // 8 warps: 4(M) x 2(N), warp tile 32x64
#define CHUNK_BYTES 16384    // one [128 rows][128B] swizzled k-chunk
#define TILE_BYTES  65536    // 128 x 256 bf16

__device__ __nv_bfloat16 g_znb[TWO_N * DDIM];
__device__ float g_rs[2 * TWO_N];   // [half][row] sum exp(2*dot) over half's cols
__device__ float g_cd[2 * TWO_N];   // [half][row] captured dot (diag or pos)

#define L2E2 2.8853900817779268f    /* 2/ln2 : exp(2d) = 2^(d*L2E2) */

// ---------------------------------------------------------------- helpers --
__device__ __forceinline__ uint32_t smem_u32(const void* p) {
    uint32_t a;
    asm("{ .reg .u64 t; cvta.to.shared.u64 t, %1; cvt.u32.u64 %0, t; }"
        : "=r"(a) : "l"(p));
    return a;
}
__device__ __forceinline__ float ex2f(float x) {
    float y; asm("ex2.approx.f32 %0, %1;" : "=f"(y) : "f"(x)); return y;
}
#define CP_ASYNC16(sm, gp) \
    asm volatile("cp.async.cg.shared.global [%0], [%1], 16;" \
                 :: "r"(sm), "l"(gp) : "memory")
#define CP_COMMIT()  asm volatile("cp.async.commit_group;" ::: "memory")
#define CP_WAIT(n)   asm volatile("cp.async.wait_group %0;" :: "n"(n) : "memory")

__device__ __forceinline__ void ldsm_x4(uint32_t* r, uint32_t addr) {
    asm volatile("ldmatrix.sync.aligned.m8n8.x4.shared.b16 {%0,%1,%2,%3}, [%4];"
                 : "=r"(r[0]), "=r"(r[1]), "=r"(r[2]), "=r"(r[3]) : "r"(addr));
}
__device__ __forceinline__ void mma16816(float* c, const uint32_t* a,
                                         uint32_t b0, uint32_t b1) {
    asm volatile(
        "mma.sync.aligned.m16n8k16.row.col.f32.bf16.bf16.f32 "
        "{%0,%1,%2,%3}, {%4,%5,%6,%7}, {%8,%9}, {%0,%1,%2,%3};"
        : "+f"(c[0]), "+f"(c[1]), "+f"(c[2]), "+f"(c[3])
        : "r"(a[0]), "r"(a[1]), "r"(a[2]), "r"(a[3]), "r"(b0), "r"(b1));
}

// ---------------------------------------------------------------------------
// Kernel 1: L2-normalize rows of concat(z1,z2) -> bf16 g_znb. 4 rows / block.
// ---------------------------------------------------------------------------
__global__ void norm_kernel(const float* __restrict__ z1,
                            const float* __restrict__ z2) {
    int tid = threadIdx.x;                 // 256
    int g = tid >> 6, t = tid & 63;
    int row = blockIdx.x * 4 + g;
    const float* src = (row < NHALF) ? (z1 + (size_t)row * DDIM)
                                     : (z2 + (size_t)(row - NHALF) * DDIM);
    float4 v = reinterpret_cast<const float4*>(src)[t];
    float ss = v.x * v.x + v.y * v.y + v.z * v.z + v.w * v.w;
#pragma unroll
    for (int o = 16; o; o >>= 1) ss += __shfl_xor_sync(0xffffffffu, ss, o);
    __shared__ float ws[8];
    if ((tid & 31) == 0) ws[tid >> 5] = ss;
    __syncthreads();
    float tot = ws[2 * g] + ws[2 * g + 1];
    float inv = 1.0f / fmaxf(sqrtf(tot), 1e-8f);
    __nv_bfloat162 p0 = __float22bfloat162_rn(make_float2(v.x * inv, v.y * inv));
    __nv_bfloat162 p1 = __float22bfloat162_rn(make_float2(v.z * inv, v.w * inv));
    __nv_bfloat162* dst =
        reinterpret_cast<__nv_bfloat162*>(g_znb + (size_t)row * DDIM + t * 4);
    dst[0] = p0; dst[1] = p1;
}

// ---------------------------------------------------------------------------
// Kernel 2: HMMA GEMM (Z Z^T block) + fused streaming exp/rowsum.
// grid = 128: blockIdx = rowblock*2 + colhalf
// ---------------------------------------------------------------------------
__global__ void __launch_bounds__(NTHR, 1) sim_kernel() {
    extern __shared__ char smem_raw[];
    char* sbase = (char*)(((uintptr_t)smem_raw + 1023) & ~(uintptr_t)1023);
    uint32_t sAu = smem_u32(sbase);              // A: 64 KB
    uint32_t sBu = sAu + TILE_BYTES;             // B: 2 x 64 KB

    __shared__ float s_rs[2][BM];                // per n-half partials
    __shared__ float s_cd[2][BM];

    int tid = threadIdx.x;
    int wid = tid >> 5, lane = tid & 31;
    int rb = blockIdx.x >> 1, h = blockIdx.x & 1;
    int rbase = rb * BM;
    int colstart = h * NHALF;
    int m_base = (wid >> 1) * 32;                // warp M offset (0,32,64,96)
    int n_base = (wid & 1) * 64;                 // warp N offset (0,64)
    int nhalf_id = wid & 1;

    // ---- issue A tile load (128 rows x 256 bf16 -> swizzled chunks) ----
    {
        const char* gA = (const char*)(g_znb + (size_t)rbase * DDIM);
#pragma unroll
        for (int i = 0; i < 16; i++) {
            int unit = i * NTHR + tid;           // row*32 + uu
            int row = unit >> 5, uu = unit & 31;
            uint32_t off = (uint32_t)(row * 128 + (uu & 7) * 16);
            off ^= (off >> 3) & 0x70;
            CP_ASYNC16(sAu + (uu >> 3) * CHUNK_BYTES + off, gA + unit * 16);
        }
        CP_COMMIT();
    }
    // ---- issue B tile 0 ----
    {
        const char* gB = (const char*)(g_znb + (size_t)colstart * DDIM);
#pragma unroll
        for (int i = 0; i < 16; i++) {
            int unit = i * NTHR + tid;
            int row = unit >> 5, uu = unit & 31;
            uint32_t off = (uint32_t)(row * 128 + (uu & 7) * 16);
            off ^= (off >> 3) & 0x70;
            CP_ASYNC16(sBu + (uu >> 3) * CHUNK_BYTES + off, gB + unit * 16);
        }
        CP_COMMIT();
    }

    // ---- per-lane ldmatrix address pieces ----
    int rA0 = m_base + (lane & 15);
    int rA1 = rA0 + 16;
    uint32_t kaddA = ((lane >> 4) & 1) * 16;     // +8 bf16 for hi lanes
    uint32_t rowA0 = (uint32_t)rA0 * 128, xA0 = (uint32_t)(rA0 & 7) << 4;
    uint32_t rowA1 = (uint32_t)rA1 * 128, xA1 = (uint32_t)(rA1 & 7) << 4;
    int rBb = n_base + (lane & 7) + ((lane & 16) >> 1);
    uint32_t kaddB = ((lane >> 3) & 1) * 16;
    uint32_t rowB[4], xB[4];
#pragma unroll
    for (int gI = 0; gI < 4; gI++) {
        int r = rBb + gI * 16;
        rowB[gI] = (uint32_t)r * 128;
        xB[gI] = (uint32_t)(r & 7) << 4;
    }

    // ---- per-thread row bookkeeping for epilogue ----
    int rowhalf = rb >> 5;
    int lrow[4], Tcol[4];
#pragma unroll
    for (int s = 0; s < 4; s++) {
        int i = s >> 1, hh = s & 1;
        int lr = m_base + i * 16 + (lane >> 2) + hh * 8;   // local row 0..127
        lrow[s] = lr;
        int row = rbase + lr;
        Tcol[s] = (h == rowhalf) ? row : (row ^ NHALF);
    }
    float prow[4] = {0.f, 0.f, 0.f, 0.f};
    float pcor[4] = {0.f, 0.f, 0.f, 0.f};

    CP_WAIT(0);
    __syncthreads();

#pragma unroll 1
    for (int t = 0; t < NTILES; t++) {
        // prefetch tile t+1
        if (t + 1 < NTILES) {
            const char* gB = (const char*)(
                g_znb + (size_t)(colstart + (t + 1) * BN) * DDIM);
            uint32_t bb = sBu + ((t + 1) & 1) * TILE_BYTES;
#pragma unroll
            for (int i = 0; i < 16; i++) {
                int unit = i * NTHR + tid;
                int row = unit >> 5, uu = unit & 31;
                uint32_t off = (uint32_t)(row * 128 + (uu & 7) * 16);
                off ^= (off >> 3) & 0x70;
                CP_ASYNC16(bb + (uu >> 3) * CHUNK_BYTES + off, gB + unit * 16);
            }
            CP_COMMIT();
            CP_WAIT(1);
        } else {
            CP_WAIT(0);
        }
        __syncthreads();

        uint32_t bbase = sBu + (t & 1) * TILE_BYTES;
        float acc[2][8][4];
#pragma unroll
        for (int i = 0; i < 2; i++)
#pragma unroll
            for (int j = 0; j < 8; j++)
#pragma unroll
                for (int q = 0; q < 4; q++) acc[i][j][q] = 0.f;

#pragma unroll
        for (int s = 0; s < 16; s++) {           // k = s*16
            uint32_t coff = (uint32_t)(s >> 2) * CHUNK_BYTES;
            uint32_t kbA = (uint32_t)(s & 3) * 32 + kaddA;
            uint32_t kbB = (uint32_t)(s & 3) * 32 + kaddB;
            uint32_t a0[4], a1[4], b[4][4];
            ldsm_x4(a0, sAu + coff + rowA0 + (kbA ^ xA0));
            ldsm_x4(a1, sAu + coff + rowA1 + (kbA ^ xA1));
#pragma unroll
            for (int gI = 0; gI < 4; gI++)
                ldsm_x4(b[gI], bbase + coff + rowB[gI] + (kbB ^ xB[gI]));
#pragma unroll
            for (int j = 0; j < 8; j++) {
                uint32_t b0 = b[j >> 1][(j & 1) * 2];
                uint32_t b1 = b[j >> 1][(j & 1) * 2 + 1];
                mma16816(acc[0][j], a0, b0, b1);
                mma16816(acc[1][j], a1, b0, b1);
            }
        }
        __syncthreads();   // done reading this B buffer

        // ---- epilogue: stream exp into per-row accumulators ----
        int colb = colstart + t * BN + n_base + (lane & 3) * 2;
#pragma unroll
        for (int i = 0; i < 2; i++)
#pragma unroll
            for (int hh = 0; hh < 2; hh++) {
                int slot = i * 2 + hh;
                float rs = 0.f;
#pragma unroll
                for (int j = 0; j < 8; j++)
#pragma unroll
                    for (int cb = 0; cb < 2; cb++) {
                        float d = acc[i][j][hh * 2 + cb];
                        rs += ex2f(d * L2E2);
                        int col = colb + j * 8 + cb;
                        pcor[slot] += (col == Tcol[slot]) ? d : 0.f;
                    }
                prow[slot] += rs;
            }
    }

    // ---- reduce 4 lanes per row, combine the two n-half warps via SMEM ----
#pragma unroll
    for (int s = 0; s < 4; s++) {
        float rs = prow[s], pc = pcor[s];
        rs += __shfl_xor_sync(0xffffffffu, rs, 1);
        rs += __shfl_xor_sync(0xffffffffu, rs, 2);
        pc += __shfl_xor_sync(0xffffffffu, pc, 1);
        pc += __shfl_xor_sync(0xffffffffu, pc, 2);
        if ((lane & 3) == 0) {
            s_rs[nhalf_id][lrow[s]] = rs;
            s_cd[nhalf_id][lrow[s]] = pc;
        }
    }
    __syncthreads();
    if (tid < BM) {
        g_rs[h * TWO_N + rbase + tid] = s_rs[0][tid] + s_rs[1][tid];
        g_cd[h * TWO_N + rbase + tid] = s_cd[0][tid] + s_cd[1][tid];
    }
}

// ---------------------------------------------------------------------------
// Kernel 3: combine halves, per-row loss, mean. One block, 1024 threads.
// ---------------------------------------------------------------------------
__global__ void finish_kernel(float* __restrict__ out) {
    int tid = threadIdx.x;
    float acc = 0.f;
#pragma unroll
    for (int i = 0; i < 8; i++) {
        int r = tid * 8 + i;
        int hr = r >> 12;                      // row's half (diag half)
        float rs = g_rs[r] + g_rs[TWO_N + r];
        float dd = g_cd[hr * TWO_N + r];       // diagonal dot (self)
        float pd = g_cd[(1 - hr) * TWO_N + r]; // positive-pair dot
        float total = rs - ex2f(dd * L2E2);    // remove self term bit-exactly
        acc += logf(total) - 2.0f * pd;
    }
#pragma unroll
    for (int o = 16; o; o >>= 1) acc += __shfl_xor_sync(0xffffffffu, acc, o);
    __shared__ float red[32];
    if ((tid & 31) == 0) red[tid >> 5] = acc;
    __syncthreads();
    if (tid < 32) {
        float v = red[tid];
#pragma unroll
        for (int o = 16; o; o >>= 1) v += __shfl_xor_sync(0xffffffffu, v, o);
        if (tid == 0) out[0] = v / (float)TWO_N;
    }
}

// ---------------------------------------------------------------------------
extern "C" void kernel_launch(void* const* d_in, const int* in_sizes, int n_in,
                              void* d_out, int out_size) {
    const float* z1 = (const float*)d_in[0];
    const float* z2 = (const float*)d_in[1];
    float* out = (float*)d_out;

    norm_kernel<<<TWO_N / 4, 256>>>(z1, z2);

    size_t smem = 3 * TILE_BYTES + 1024;   // 197,632 B
    cudaFuncSetAttribute(sim_kernel, cudaFuncAttributeMaxDynamicSharedMemorySize,
                         (int)smem);
    sim_kernel<<<128, NTHR, smem>>>();

    finish_kernel<<<1, 1024>>>(out);
}

// round 5
// speedup vs baseline: 13.8667x; 1.5487x over previous
#include <cuda_runtime.h>
#include <cuda_bf16.h>
#include <cstdint>

#define TWO_N 8192
#define NHALF 4096
#define DDIM  256
#define BM 128
#define NBLK 2080            // 64*65/2 upper-triangle 128x128 blocks
#define NCTA 148
#define NTHR 256             // 8 warps: 4(M) x 2(N), warp tile 32x64
#define CHUNK_BYTES 16384    // one [128 rows][128B] swizzled k-chunk
#define TILE_BYTES  65536    // 128 x 256 bf16

__device__ __nv_bfloat16 g_znb[TWO_N * DDIM];
__device__ float g_pr[(size_t)NBLK * 128];  // per-block row partial sums
__device__ float g_pc[(size_t)NBLK * 128];  // per-block col partial sums
__device__ float g_cdd[TWO_N];              // self dot per row
__device__ float g_cdp[TWO_N];              // positive-pair dot per row
__device__ float g_bs[64];                  // per-rowblock loss partial

#define L2E2 2.8853900817779268f    /* 2/ln2 : exp(2d) = 2^(d*L2E2) */

// ---------------------------------------------------------------- helpers --
__device__ __forceinline__ uint32_t smem_u32(const void* p) {
    uint32_t a;
    asm("{ .reg .u64 t; cvta.to.shared.u64 t, %1; cvt.u32.u64 %0, t; }"
        : "=r"(a) : "l"(p));
    return a;
}
__device__ __forceinline__ float ex2f(float x) {
    float y; asm("ex2.approx.f32 %0, %1;" : "=f"(y) : "f"(x)); return y;
}
#define CP_ASYNC16(sm, gp) \
    asm volatile("cp.async.cg.shared.global [%0], [%1], 16;" \
                 :: "r"(sm), "l"(gp) : "memory")
#define CP_COMMIT()  asm volatile("cp.async.commit_group;" ::: "memory")
#define CP_WAIT(n)   asm volatile("cp.async.wait_group %0;" :: "n"(n) : "memory")

__device__ __forceinline__ void ldsm_x4(uint32_t* r, uint32_t addr) {
    asm volatile("ldmatrix.sync.aligned.m8n8.x4.shared.b16 {%0,%1,%2,%3}, [%4];"
                 : "=r"(r[0]), "=r"(r[1]), "=r"(r[2]), "=r"(r[3]) : "r"(addr));
}
__device__ __forceinline__ void mma16816(float* c, const uint32_t* a,
                                         uint32_t b0, uint32_t b1) {
    asm volatile(
        "mma.sync.aligned.m16n8k16.row.col.f32.bf16.bf16.f32 "
        "{%0,%1,%2,%3}, {%4,%5,%6,%7}, {%8,%9}, {%0,%1,%2,%3};"
        : "+f"(c[0]), "+f"(c[1]), "+f"(c[2]), "+f"(c[3])
        : "r"(a[0]), "r"(a[1]), "r"(a[2]), "r"(a[3]), "r"(b0), "r"(b1));
}

// upper-triangle block id in paired-strip order
__device__ __forceinline__ int bidx(int I, int J) {   // I <= J
    return (I < 32) ? (64 * I + J) : (65 * (63 - I) + I + 1 + (J - I));
}
__device__ __forceinline__ void bdecode(int g, int& I, int& J) {
    int p = g / 65, r = g - p * 65;
    if (r < 64 - p) { I = p;      J = p + r; }
    else            { I = 63 - p; J = I + (r - (64 - p)); }
}

// ---------------------------------------------------------------------------
// Kernel 1: L2-normalize rows of concat(z1,z2) -> bf16 g_znb. 4 rows / block.
// ---------------------------------------------------------------------------
__global__ void norm_kernel(const float* __restrict__ z1,
                            const float* __restrict__ z2) {
    int tid = threadIdx.x;                 // 256
    int g = tid >> 6, t = tid & 63;
    int row = blockIdx.x * 4 + g;
    const float* src = (row < NHALF) ? (z1 + (size_t)row * DDIM)
                                     : (z2 + (size_t)(row - NHALF) * DDIM);
    float4 v = reinterpret_cast<const float4*>(src)[t];
    float ss = v.x * v.x + v.y * v.y + v.z * v.z + v.w * v.w;
#pragma unroll
    for (int o = 16; o; o >>= 1) ss += __shfl_xor_sync(0xffffffffu, ss, o);
    __shared__ float ws[8];
    if ((tid & 31) == 0) ws[tid >> 5] = ss;
    __syncthreads();
    float tot = ws[2 * g] + ws[2 * g + 1];
    float inv = 1.0f / fmaxf(sqrtf(tot), 1e-8f);
    __nv_bfloat162 p0 = __float22bfloat162_rn(make_float2(v.x * inv, v.y * inv));
    __nv_bfloat162 p1 = __float22bfloat162_rn(make_float2(v.z * inv, v.w * inv));
    __nv_bfloat162* dst =
        reinterpret_cast<__nv_bfloat162*>(g_znb + (size_t)row * DDIM + t * 4);
    dst[0] = p0; dst[1] = p1;
}

// ---------------------------------------------------------------------------
// tile loader: 128 rows x 256 bf16 -> swizzled k-chunks via cp.async
// ---------------------------------------------------------------------------
__device__ __forceinline__ void load_tile(uint32_t sdst, int rowblk, int tid) {
    const char* gsrc = (const char*)(g_znb + (size_t)rowblk * BM * DDIM);
#pragma unroll
    for (int i = 0; i < 16; i++) {
        int unit = i * NTHR + tid;           // row*32 + uu
        int row = unit >> 5, uu = unit & 31;
        uint32_t off = (uint32_t)(row * 128 + (uu & 7) * 16);
        off ^= (off >> 3) & 0x70;
        CP_ASYNC16(sdst + (uu >> 3) * CHUNK_BYTES + off, gsrc + unit * 16);
    }
}

// ---------------------------------------------------------------------------
// Kernel 2: symmetric HMMA GEMM over upper-triangle blocks + fused exp sums.
// grid = 148 persistent CTAs over 2080 blocks in paired-strip order.
// ---------------------------------------------------------------------------
__global__ void __launch_bounds__(NTHR, 1) sim_kernel() {
    extern __shared__ char smem_raw[];
    char* sbase = (char*)(((uintptr_t)smem_raw + 1023) & ~(uintptr_t)1023);
    uint32_t sAu = smem_u32(sbase);              // A: 64 KB (single)
    uint32_t sBu = sAu + TILE_BYTES;             // B: 2 x 64 KB

    __shared__ float s_rs[2][BM];                // n-half rowsum partials
    __shared__ float s_cs[8][64];                // [mwarp*2+nhalf][col]

    int tid = threadIdx.x;
    int wid = tid >> 5, lane = tid & 31;
    int cta = blockIdx.x;
    int start = cta * 14 + (cta < 8 ? cta : 8);
    int cnt = 14 + (cta < 8 ? 1 : 0);

    int m_base = (wid >> 1) * 32;
    int n_base = (wid & 1) * 64;
    int mwarp = wid >> 1, nhalf = wid & 1;

    // ---- per-lane ldmatrix address pieces (same mapping as before) ----
    int rA0 = m_base + (lane & 15);
    int rA1 = rA0 + 16;
    uint32_t kaddA = ((lane >> 4) & 1) * 16;
    uint32_t rowA0 = (uint32_t)rA0 * 128, xA0 = (uint32_t)(rA0 & 7) << 4;
    uint32_t rowA1 = (uint32_t)rA1 * 128, xA1 = (uint32_t)(rA1 & 7) << 4;
    int rBb = n_base + (lane & 7) + ((lane & 16) >> 1);
    uint32_t kaddB = ((lane >> 3) & 1) * 16;
    uint32_t rowB[4], xB[4];
#pragma unroll
    for (int gI = 0; gI < 4; gI++) {
        int r = rBb + gI * 16;
        rowB[gI] = (uint32_t)r * 128;
        xB[gI] = (uint32_t)(r & 7) << 4;
    }
    int lrow[4];
#pragma unroll
    for (int s = 0; s < 4; s++)
        lrow[s] = m_base + (s >> 1) * 16 + (lane >> 2) + (s & 1) * 8;

    // ---- prologue: first A and first B ----
    int I0, J0; bdecode(start, I0, J0);
    load_tile(sAu, I0, tid); CP_COMMIT();
    load_tile(sBu, J0, tid); CP_COMMIT();
    int curI = I0;

#pragma unroll 1
    for (int n = 0; n < cnt; n++) {
        int I, J; bdecode(start + n, I, J);
        int In = -1, Jn = -1;
        if (n + 1 < cnt) {
            bdecode(start + n + 1, In, Jn);
            load_tile(sBu + ((n + 1) & 1) * TILE_BYTES, Jn, tid);
            CP_COMMIT();
            CP_WAIT(1);          // current A + current B arrived
        } else {
            CP_WAIT(0);
        }
        __syncthreads();

        // ---- MMA: 128x128 block, K=256 ----
        uint32_t bbase = sBu + (n & 1) * TILE_BYTES;
        float acc[2][8][4];
#pragma unroll
        for (int i = 0; i < 2; i++)
#pragma unroll
            for (int j = 0; j < 8; j++)
#pragma unroll
                for (int q = 0; q < 4; q++) acc[i][j][q] = 0.f;

#pragma unroll
        for (int s = 0; s < 16; s++) {           // k = s*16
            uint32_t coff = (uint32_t)(s >> 2) * CHUNK_BYTES;
            uint32_t kbA = (uint32_t)(s & 3) * 32 + kaddA;
            uint32_t kbB = (uint32_t)(s & 3) * 32 + kaddB;
            uint32_t a0[4], a1[4], b[4][4];
            ldsm_x4(a0, sAu + coff + rowA0 + (kbA ^ xA0));
            ldsm_x4(a1, sAu + coff + rowA1 + (kbA ^ xA1));
#pragma unroll
            for (int gI = 0; gI < 4; gI++)
                ldsm_x4(b[gI], bbase + coff + rowB[gI] + (kbB ^ xB[gI]));
#pragma unroll
            for (int j = 0; j < 8; j++) {
                uint32_t b0 = b[j >> 1][(j & 1) * 2];
                uint32_t b1 = b[j >> 1][(j & 1) * 2 + 1];
                mma16816(acc[0][j], a0, b0, b1);
                mma16816(acc[1][j], a1, b0, b1);
            }
        }
        __syncthreads();   // sA / sB[n&1] no longer read

        // issue A reload for next block (overlaps epilogue)
        if (In >= 0 && In != curI) {
            load_tile(sAu, In, tid);
            CP_COMMIT();
            curI = In;
        }

        // ---- epilogue: exp, row sums, col sums, captures ----
        bool diag = (I == J);
        bool pairb = (J == I + 32);
        float rs[4] = {0.f, 0.f, 0.f, 0.f};
        float cs[8][2];
#pragma unroll
        for (int j = 0; j < 8; j++) { cs[j][0] = 0.f; cs[j][1] = 0.f; }

#pragma unroll
        for (int i = 0; i < 2; i++)
#pragma unroll
            for (int hh = 0; hh < 2; hh++) {
                int slot = i * 2 + hh;
                float racc = 0.f;
#pragma unroll
                for (int j = 0; j < 8; j++)
#pragma unroll
                    for (int cb = 0; cb < 2; cb++) {
                        float d = acc[i][j][hh * 2 + cb];
                        float e = ex2f(d * L2E2);
                        racc += e;
                        cs[j][cb] += e;
                        if (diag || pairb) {
                            int lc = n_base + j * 8 + (lane & 3) * 2 + cb;
                            if (lc == lrow[slot]) {       // local diagonal
                                int rg = I * BM + lrow[slot];
                                if (diag) g_cdd[rg] = d;
                                else { g_cdp[rg] = d;
                                       g_cdp[J * BM + lrow[slot]] = d; }
                            }
                        }
                    }
                rs[slot] += racc;
            }

        // rowsum: reduce 4 lanes sharing each row, stash per n-half
#pragma unroll
        for (int s = 0; s < 4; s++) {
            float v = rs[s];
            v += __shfl_xor_sync(0xffffffffu, v, 1);
            v += __shfl_xor_sync(0xffffffffu, v, 2);
            if ((lane & 3) == 0) s_rs[nhalf][lrow[s]] = v;
        }
        // colsum: reduce over rows (lanes with same lane&3), stash per m-warp
        if (!diag) {
#pragma unroll
            for (int j = 0; j < 8; j++)
#pragma unroll
                for (int cb = 0; cb < 2; cb++) {
                    float v = cs[j][cb];
                    v += __shfl_xor_sync(0xffffffffu, v, 4);
                    v += __shfl_xor_sync(0xffffffffu, v, 8);
                    v += __shfl_xor_sync(0xffffffffu, v, 16);
                    if (lane < 4)
                        s_cs[mwarp * 2 + nhalf][j * 8 + lane * 2 + cb] = v;
                }
        }
        __syncthreads();

        if (tid < BM) {
            size_t boff = (size_t)(start + n) * 128 + tid;
            g_pr[boff] = s_rs[0][tid] + s_rs[1][tid];
            if (!diag) {
                int nh = tid >> 6, cc = tid & 63;
                g_pc[boff] = s_cs[0 * 2 + nh][cc] + s_cs[1 * 2 + nh][cc] +
                             s_cs[2 * 2 + nh][cc] + s_cs[3 * 2 + nh][cc];
            }
        }
    }
}

// ---------------------------------------------------------------------------
// Kernel 3: per-row combine of 64 partials -> per-rowblock loss sum
// ---------------------------------------------------------------------------
__global__ void reduce1_kernel() {
    int R = blockIdx.x, q = threadIdx.x;     // 64 blocks x 128 threads
    int r = R * 128 + q;
    float tot = 0.f;
#pragma unroll 4
    for (int J = R; J < 64; J++) tot += g_pr[(size_t)bidx(R, J) * 128 + q];
#pragma unroll 4
    for (int I = 0; I < R; I++)  tot += g_pc[(size_t)bidx(I, R) * 128 + q];
    tot -= ex2f(g_cdd[r] * L2E2);            // remove self term
    float lv = logf(tot) - 2.0f * g_cdp[r];

    int lane = q & 31;
#pragma unroll
    for (int o = 16; o; o >>= 1) lv += __shfl_xor_sync(0xffffffffu, lv, o);
    __shared__ float w[4];
    if (lane == 0) w[q >> 5] = lv;
    __syncthreads();
    if (q == 0) g_bs[R] = w[0] + w[1] + w[2] + w[3];
}

// ---------------------------------------------------------------------------
// Kernel 4: final mean
// ---------------------------------------------------------------------------
__global__ void reduce2_kernel(float* __restrict__ out) {
    int t = threadIdx.x;                     // 64 threads
    float v = g_bs[t];
#pragma unroll
    for (int o = 16; o; o >>= 1) v += __shfl_xor_sync(0xffffffffu, v, o);
    __shared__ float a[2];
    if ((t & 31) == 0) a[t >> 5] = v;
    __syncthreads();
    if (t == 0) out[0] = (a[0] + a[1]) / (float)TWO_N;
}

// ---------------------------------------------------------------------------
extern "C" void kernel_launch(void* const* d_in, const int* in_sizes, int n_in,
                              void* d_out, int out_size) {
    const float* z1 = (const float*)d_in[0];
    const float* z2 = (const float*)d_in[1];
    float* out = (float*)d_out;

    norm_kernel<<<TWO_N / 4, 256>>>(z1, z2);

    size_t smem = 3 * TILE_BYTES + 1024;   // 197,632 B
    cudaFuncSetAttribute(sim_kernel, cudaFuncAttributeMaxDynamicSharedMemorySize,
                         (int)smem);
    sim_kernel<<<NCTA, NTHR, smem>>>();

    reduce1_kernel<<<64, 128>>>();
    reduce2_kernel<<<1, 64>>>(out);
}

// round 6
// speedup vs baseline: 14.9991x; 1.0817x over previous
#include <cuda_runtime.h>
#include <cuda_bf16.h>
#include <cstdint>

#define TWO_N 8192
#define NHALF 4096
#define DDIM  256
#define BM 128
#define NBLK 2080            // 64*65/2 upper-triangle 128x128 blocks
#define NCTA 148
#define NTHR 256             // 8 warps: 4(M) x 2(N), warp tile 32x64
#define CHUNK_BYTES 16384    // one [128 rows][128B] swizzled k-chunk
#define TILE_BYTES  65536    // 128 x 256 bf16

__device__ __nv_bfloat16 g_znb[TWO_N * DDIM];
__device__ float g_pr[(size_t)NBLK * 128];  // per-block row partial sums
__device__ float g_pc[(size_t)NBLK * 128];  // per-block col partial sums
__device__ float g_cdd[TWO_N];              // self dot per row
__device__ float g_cdp[TWO_N];              // positive-pair dot per row
__device__ float g_bs[64];                  // per-rowblock loss partial
__device__ int   g_cnt;                     // last-block counter

#define L2E2 2.8853900817779268f    /* 2/ln2 : exp(2d) = 2^(d*L2E2) */

// ---------------------------------------------------------------- helpers --
__device__ __forceinline__ uint32_t smem_u32(const void* p) {
    uint32_t a;
    asm("{ .reg .u64 t; cvta.to.shared.u64 t, %1; cvt.u32.u64 %0, t; }"
        : "=r"(a) : "l"(p));
    return a;
}
__device__ __forceinline__ float ex2f(float x) {
    float y; asm("ex2.approx.f32 %0, %1;" : "=f"(y) : "f"(x)); return y;
}
#define CP_ASYNC16(sm, gp) \
    asm volatile("cp.async.cg.shared.global [%0], [%1], 16;" \
                 :: "r"(sm), "l"(gp) : "memory")
#define CP_COMMIT()  asm volatile("cp.async.commit_group;" ::: "memory")
#define CP_WAIT(n)   asm volatile("cp.async.wait_group %0;" :: "n"(n) : "memory")

__device__ __forceinline__ void ldsm_x4(uint32_t* r, uint32_t addr) {
    asm volatile("ldmatrix.sync.aligned.m8n8.x4.shared.b16 {%0,%1,%2,%3}, [%4];"
                 : "=r"(r[0]), "=r"(r[1]), "=r"(r[2]), "=r"(r[3]) : "r"(addr));
}
__device__ __forceinline__ void mma16816(float* c, const uint32_t* a,
                                         uint32_t b0, uint32_t b1) {
    asm volatile(
        "mma.sync.aligned.m16n8k16.row.col.f32.bf16.bf16.f32 "
        "{%0,%1,%2,%3}, {%4,%5,%6,%7}, {%8,%9}, {%0,%1,%2,%3};"
        : "+f"(c[0]), "+f"(c[1]), "+f"(c[2]), "+f"(c[3])
        : "r"(a[0]), "r"(a[1]), "r"(a[2]), "r"(a[3]), "r"(b0), "r"(b1));
}

// upper-triangle block id in paired-strip order
__device__ __forceinline__ int bidx(int I, int J) {   // I <= J
    return (I < 32) ? (64 * I + J) : (65 * (63 - I) + I + 1 + (J - I));
}
__device__ __forceinline__ void bdecode(int g, int& I, int& J) {
    int p = g / 65, r = g - p * 65;
    if (r < 64 - p) { I = p;      J = p + r; }
    else            { I = 63 - p; J = I + (r - (64 - p)); }
}

// ---------------------------------------------------------------------------
// Kernel 1: L2-normalize rows -> bf16. One warp per row, no smem.
// ---------------------------------------------------------------------------
__global__ void norm_kernel(const float* __restrict__ z1,
                            const float* __restrict__ z2) {
    int wid = threadIdx.x >> 5, lane = threadIdx.x & 31;
    int row = blockIdx.x * 8 + wid;
    const float4* src = reinterpret_cast<const float4*>(
        (row < NHALF) ? (z1 + (size_t)row * DDIM)
                      : (z2 + (size_t)(row - NHALF) * DDIM));
    float4 v0 = src[lane];
    float4 v1 = src[lane + 32];
    float ss = v0.x * v0.x + v0.y * v0.y + v0.z * v0.z + v0.w * v0.w
             + v1.x * v1.x + v1.y * v1.y + v1.z * v1.z + v1.w * v1.w;
#pragma unroll
    for (int o = 16; o; o >>= 1) ss += __shfl_xor_sync(0xffffffffu, ss, o);
    float inv = 1.0f / fmaxf(sqrtf(ss), 1e-8f);
    uint32_t a0, a1, b0, b1;
    asm("cvt.rn.bf16x2.f32 %0, %1, %2;" : "=r"(a0) : "f"(v0.y * inv), "f"(v0.x * inv));
    asm("cvt.rn.bf16x2.f32 %0, %1, %2;" : "=r"(a1) : "f"(v0.w * inv), "f"(v0.z * inv));
    asm("cvt.rn.bf16x2.f32 %0, %1, %2;" : "=r"(b0) : "f"(v1.y * inv), "f"(v1.x * inv));
    asm("cvt.rn.bf16x2.f32 %0, %1, %2;" : "=r"(b1) : "f"(v1.w * inv), "f"(v1.z * inv));
    uint2* dst = reinterpret_cast<uint2*>(g_znb + (size_t)row * DDIM);
    dst[lane]      = make_uint2(a0, a1);
    dst[lane + 32] = make_uint2(b0, b1);
}

// ---------------------------------------------------------------------------
// tile loader: 128 rows x 256 bf16 -> swizzled k-chunks via cp.async
// ---------------------------------------------------------------------------
__device__ __forceinline__ void load_tile(uint32_t sdst, int rowblk, int tid) {
    const char* gsrc = (const char*)(g_znb + (size_t)rowblk * BM * DDIM);
#pragma unroll
    for (int i = 0; i < 16; i++) {
        int unit = i * NTHR + tid;           // row*32 + uu
        int row = unit >> 5, uu = unit & 31;
        uint32_t off = (uint32_t)(row * 128 + (uu & 7) * 16);
        off ^= (off >> 3) & 0x70;
        CP_ASYNC16(sdst + (uu >> 3) * CHUNK_BYTES + off, gsrc + unit * 16);
    }
}

// ---------------------------------------------------------------------------
// Kernel 2: symmetric HMMA GEMM over upper-triangle blocks, deferred epilogue.
// grid = 148 persistent CTAs over 2080 blocks in paired-strip order.
// ---------------------------------------------------------------------------
__global__ void __launch_bounds__(NTHR, 1) sim_kernel() {
    extern __shared__ char smem_raw[];
    char* sbase = (char*)(((uintptr_t)smem_raw + 1023) & ~(uintptr_t)1023);
    uint32_t sAu = smem_u32(sbase);              // A: 64 KB (single)
    uint32_t sBu = sAu + TILE_BYTES;             // B: 2 x 64 KB

    __shared__ float s_rs[2][BM];                // n-half rowsum partials
    __shared__ float s_cs[8][64];                // [mwarp*2+nhalf][col]

    int tid = threadIdx.x;
    int wid = tid >> 5, lane = tid & 31;
    int cta = blockIdx.x;
    int start = cta * 14 + (cta < 8 ? cta : 8);
    int cnt = 14 + (cta < 8 ? 1 : 0);

    int m_base = (wid >> 1) * 32;
    int n_base = (wid & 1) * 64;
    int mwarp = wid >> 1, nhalf = wid & 1;

    // ---- per-lane ldmatrix address pieces ----
    int rA0 = m_base + (lane & 15);
    int rA1 = rA0 + 16;
    uint32_t kaddA = ((lane >> 4) & 1) * 16;
    uint32_t rowA0 = (uint32_t)rA0 * 128, xA0 = (uint32_t)(rA0 & 7) << 4;
    uint32_t rowA1 = (uint32_t)rA1 * 128, xA1 = (uint32_t)(rA1 & 7) << 4;
    int rBb = n_base + (lane & 7) + ((lane & 16) >> 1);
    uint32_t kaddB = ((lane >> 3) & 1) * 16;
    uint32_t rowB[4], xB[4];
#pragma unroll
    for (int gI = 0; gI < 4; gI++) {
        int r = rBb + gI * 16;
        rowB[gI] = (uint32_t)r * 128;
        xB[gI] = (uint32_t)(r & 7) << 4;
    }
    int lrow[4];
#pragma unroll
    for (int s = 0; s < 4; s++)
        lrow[s] = m_base + (s >> 1) * 16 + (lane >> 2) + (s & 1) * 8;
    int lcb = n_base + (lane & 3) * 2;           // base local col of this lane

    float accA[2][8][4], accB[2][8][4];
    float rs[4] = {0.f, 0.f, 0.f, 0.f};
    float cs[8][2];
#pragma unroll
    for (int j = 0; j < 8; j++) { cs[j][0] = 0.f; cs[j][1] = 0.f; }
    int curI;

    // write reduced old-block results (called with do_old block's I,J and
    // partial-sum registers already reduced into rs/cs)
    auto flush_old = [&](int oI, int oJ, int oblk) {
#pragma unroll
        for (int s2 = 0; s2 < 4; s2++) {
            float v = rs[s2];
            v += __shfl_xor_sync(0xffffffffu, v, 1);
            v += __shfl_xor_sync(0xffffffffu, v, 2);
            if ((lane & 3) == 0) s_rs[nhalf][lrow[s2]] = v;
        }
        if (oI != oJ) {
#pragma unroll
            for (int j = 0; j < 8; j++)
#pragma unroll
                for (int cb = 0; cb < 2; cb++) {
                    float v = cs[j][cb];
                    v += __shfl_xor_sync(0xffffffffu, v, 4);
                    v += __shfl_xor_sync(0xffffffffu, v, 8);
                    v += __shfl_xor_sync(0xffffffffu, v, 16);
                    if (lane < 4)
                        s_cs[mwarp * 2 + nhalf][j * 8 + lane * 2 + cb] = v;
                }
        }
        __syncthreads();
        if (tid < BM) {
            size_t boff = (size_t)oblk * 128 + tid;
            g_pr[boff] = s_rs[0][tid] + s_rs[1][tid];
            if (oI != oJ) {
                int nh = tid >> 6, cc = tid & 63;
                g_pc[boff] = s_cs[nh][cc] + s_cs[2 + nh][cc] +
                             s_cs[4 + nh][cc] + s_cs[6 + nh][cc];
            }
        }
#pragma unroll
        for (int s2 = 0; s2 < 4; s2++) rs[s2] = 0.f;
#pragma unroll
        for (int j = 0; j < 8; j++) { cs[j][0] = 0.f; cs[j][1] = 0.f; }
    };

    // one GEMM block with interleaved epilogue of the previous block
    auto run_block = [&](float (&acc)[2][8][4], float (&aold)[2][8][4],
                         int n, int oI, int oJ, bool do_old) {
        if (n + 1 < cnt) {
            int In, Jn; bdecode(start + n + 1, In, Jn);
            load_tile(sBu + ((n + 1) & 1) * TILE_BYTES, Jn, tid);
            CP_COMMIT();
            CP_WAIT(1);
        } else {
            CP_WAIT(0);
        }
        __syncthreads();

#pragma unroll
        for (int i = 0; i < 2; i++)
#pragma unroll
            for (int j = 0; j < 8; j++)
#pragma unroll
                for (int q = 0; q < 4; q++) acc[i][j][q] = 0.f;

        uint32_t bbase = sBu + (n & 1) * TILE_BYTES;
        bool isdiag = (oI == oJ);
        bool capb = do_old && (isdiag || oJ == oI + 32);

#pragma unroll
        for (int s = 0; s < 16; s++) {           // k = s*16
            uint32_t coff = (uint32_t)(s >> 2) * CHUNK_BYTES;
            uint32_t kbA = (uint32_t)(s & 3) * 32 + kaddA;
            uint32_t kbB = (uint32_t)(s & 3) * 32 + kaddB;
            uint32_t a0[4], a1[4], b[4][4];
            ldsm_x4(a0, sAu + coff + rowA0 + (kbA ^ xA0));
            ldsm_x4(a1, sAu + coff + rowA1 + (kbA ^ xA1));
#pragma unroll
            for (int gI = 0; gI < 4; gI++)
                ldsm_x4(b[gI], bbase + coff + rowB[gI] + (kbB ^ xB[gI]));

            // deferred epilogue chunk: element (ii, jj) of old block
            if (do_old) {
                const int ii = s >> 3, jj = s & 7;
#pragma unroll
                for (int q = 0; q < 4; q++) {
                    float d = aold[ii][jj][q];
                    float e = ex2f(d * L2E2);
                    rs[ii * 2 + (q >> 1)] += e;
                    cs[jj][q & 1] += e;
                    if (capb) {
                        int slot = ii * 2 + (q >> 1);
                        int lc = lcb + jj * 8 + (q & 1);
                        if (lc == lrow[slot]) {
                            int rg = oI * BM + lrow[slot];
                            if (isdiag) g_cdd[rg] = d;
                            else { g_cdp[rg] = d;
                                   g_cdp[oJ * BM + lrow[slot]] = d; }
                        }
                    }
                }
            }

#pragma unroll
            for (int j = 0; j < 8; j++) {
                uint32_t b0 = b[j >> 1][(j & 1) * 2];
                uint32_t b1 = b[j >> 1][(j & 1) * 2 + 1];
                mma16816(acc[0][j], a0, b0, b1);
                mma16816(acc[1][j], a1, b0, b1);
            }
        }
        __syncthreads();   // sA / sB[n&1] no longer read

        if (n + 1 < cnt) {
            int In, Jn; bdecode(start + n + 1, In, Jn);
            if (In != curI) { load_tile(sAu, In, tid); CP_COMMIT(); curI = In; }
        }
        if (do_old) flush_old(oI, oJ, start + n - 1);
    };

    // ---- prologue ----
    int I0, J0; bdecode(start, I0, J0);
    load_tile(sAu, I0, tid); CP_COMMIT();
    load_tile(sBu, J0, tid); CP_COMMIT();
    curI = I0;

    bool useA = true;
    int pI = 0, pJ = 0;
#pragma unroll 1
    for (int n = 0; n < cnt; n++) {
        int I, J; bdecode(start + n, I, J);
        if (useA) run_block(accA, accB, n, pI, pJ, n > 0);
        else      run_block(accB, accA, n, pI, pJ, n > 0);
        useA = !useA; pI = I; pJ = J;
    }

    // ---- final (non-interleaved) epilogue for the last block ----
    {
        __syncthreads();                         // s_rs/s_cs safe to rewrite
        bool isdiag = (pI == pJ);
        bool capb = isdiag || (pJ == pI + 32);
#pragma unroll
        for (int ii = 0; ii < 2; ii++)
#pragma unroll
            for (int jj = 0; jj < 8; jj++)
#pragma unroll
                for (int q = 0; q < 4; q++) {
                    float d = useA ? accB[ii][jj][q] : accA[ii][jj][q];
                    float e = ex2f(d * L2E2);
                    rs[ii * 2 + (q >> 1)] += e;
                    cs[jj][q & 1] += e;
                    if (capb) {
                        int slot = ii * 2 + (q >> 1);
                        int lc = lcb + jj * 8 + (q & 1);
                        if (lc == lrow[slot]) {
                            int rg = pI * BM + lrow[slot];
                            if (isdiag) g_cdd[rg] = d;
                            else { g_cdp[rg] = d;
                                   g_cdp[pJ * BM + lrow[slot]] = d; }
                        }
                    }
                }
        flush_old(pI, pJ, start + cnt - 1);
    }
}

// ---------------------------------------------------------------------------
// Kernel 3: per-row combine of partials -> loss; last block does final mean.
// ---------------------------------------------------------------------------
__global__ void reduce_kernel(float* __restrict__ out) {
    int R = blockIdx.x, q = threadIdx.x;     // 64 blocks x 128 threads
    int r = R * 128 + q;
    float tot = 0.f;
#pragma unroll 4
    for (int J = R; J < 64; J++) tot += g_pr[(size_t)bidx(R, J) * 128 + q];
#pragma unroll 4
    for (int I = 0; I < R; I++)  tot += g_pc[(size_t)bidx(I, R) * 128 + q];
    tot -= ex2f(g_cdd[r] * L2E2);            // remove self term
    float lv = logf(tot) - 2.0f * g_cdp[r];

    int lane = q & 31;
#pragma unroll
    for (int o = 16; o; o >>= 1) lv += __shfl_xor_sync(0xffffffffu, lv, o);
    __shared__ float w[4];
    __shared__ int slast;
    __shared__ float aa[2];
    if (lane == 0) w[q >> 5] = lv;
    __syncthreads();
    if (q == 0) {
        g_bs[R] = w[0] + w[1] + w[2] + w[3];
        __threadfence();
        slast = (atomicAdd(&g_cnt, 1) == 63);
    }
    __syncthreads();
    if (slast) {
        __threadfence();
        if (q < 64) {
            float v = g_bs[q];
#pragma unroll
            for (int o = 16; o; o >>= 1) v += __shfl_xor_sync(0xffffffffu, v, o);
            if ((q & 31) == 0) aa[q >> 5] = v;
        }
        __syncthreads();
        if (q == 0) {
            out[0] = (aa[0] + aa[1]) / (float)TWO_N;
            g_cnt = 0;                       // reset for graph replay
        }
    }
}

// ---------------------------------------------------------------------------
extern "C" void kernel_launch(void* const* d_in, const int* in_sizes, int n_in,
                              void* d_out, int out_size) {
    const float* z1 = (const float*)d_in[0];
    const float* z2 = (const float*)d_in[1];
    float* out = (float*)d_out;

    norm_kernel<<<TWO_N / 8, 256>>>(z1, z2);

    size_t smem = 3 * TILE_BYTES + 1024;   // 197,632 B
    cudaFuncSetAttribute(sim_kernel, cudaFuncAttributeMaxDynamicSharedMemorySize,
                         (int)smem);
    sim_kernel<<<NCTA, NTHR, smem>>>();

    reduce_kernel<<<64, 128>>>(out);
}